// round 6
// baseline (speedup 1.0000x reference)
#include <cuda_runtime.h>
#include <math.h>

#define H      768
#define BATCH  16
#define SEQ    4096
#define NCHUNK 32
#define CHUNK  (SEQ / NCHUNK)      // 128
#define NT     192                 // main_pass threads (768/4)
#define NW     (NT / 32)           // 6 warps
#define G      8                   // tokens per group
#define SCALE  0.03608439182435161f  // 768^-0.5

// ---------------- scratch (static device arrays, allowed) ----------------
__device__ float g_psum [BATCH][NCHUNK][H];
__device__ float g_pmax [BATCH][NCHUNK][H];
__device__ float g_pmin [BATCH][NCHUNK][H];
__device__ float g_pacc0[BATCH][NCHUNK][H];
__device__ float g_pacc1[BATCH][NCHUNK][H];
__device__ float g_pm   [BATCH][NCHUNK][2];
__device__ float g_pl   [BATCH][NCHUNK][2];
__device__ float g_pooled[2][BATCH][3 * H];  // [0]=trad(mean|max|min), [1]=learn(pmp0|pmp1|clf)
__device__ float g_hid   [2][BATCH][H];

// ---------------- kernel 1: fused LN + online-softmax-attn + pooling ----------------
__global__ __launch_bounds__(NT, 2) void main_pass(
    const float* __restrict__ tokens, const int* __restrict__ lengths,
    const float* __restrict__ q, const float* __restrict__ ln_g,
    const float* __restrict__ ln_b)
{
    const int b = blockIdx.y, c = blockIdx.x, t = threadIdx.x;
    const int wid = t >> 5, lane = t & 31;
    const int h0 = 4 * t;
    __shared__ float  sredS[2][NW][32];   // double-buffered: 1 barrier per group
    __shared__ float4 sred4[NW];

    const int len = lengths[b];
    const int s0  = c * CHUNK;
    const int s1  = min(s0 + CHUNK, len);

    const float4 gv  = *(const float4*)&ln_g[h0];
    const float4 lbv = *(const float4*)&ln_b[h0];
    const float4 q0v = *(const float4*)&q[h0];
    const float4 q1v = *(const float4*)&q[H + h0];
    const float4 qg0 = make_float4(q0v.x * gv.x, q0v.y * gv.y, q0v.z * gv.z, q0v.w * gv.w);
    const float4 qg1 = make_float4(q1v.x * gv.x, q1v.y * gv.y, q1v.z * gv.z, q1v.w * gv.w);

    // block-wide constants S0,S1,C0,C1
    float S0, S1, C0, C1;
    {
        float a = (qg0.x + qg0.y) + (qg0.z + qg0.w);
        float d = (qg1.x + qg1.y) + (qg1.z + qg1.w);
        float e = fmaf(q0v.x, lbv.x, fmaf(q0v.y, lbv.y, fmaf(q0v.z, lbv.z, q0v.w * lbv.w)));
        float f = fmaf(q1v.x, lbv.x, fmaf(q1v.y, lbv.y, fmaf(q1v.z, lbv.z, q1v.w * lbv.w)));
#pragma unroll
        for (int o = 16; o > 0; o >>= 1) {
            a += __shfl_xor_sync(0xffffffffu, a, o);
            d += __shfl_xor_sync(0xffffffffu, d, o);
            e += __shfl_xor_sync(0xffffffffu, e, o);
            f += __shfl_xor_sync(0xffffffffu, f, o);
        }
        if (lane == 0) sred4[wid] = make_float4(a, d, e, f);
        __syncthreads();
        float4 v = sred4[0];
#pragma unroll
        for (int w = 1; w < NW; w++) {
            float4 u = sred4[w]; v.x += u.x; v.y += u.y; v.z += u.z; v.w += u.w;
        }
        S0 = v.x; S1 = v.y; C0 = v.z; C1 = v.w;
        __syncthreads();
    }

    float4 accS  = make_float4(0.f, 0.f, 0.f, 0.f);
    float4 acc0p = make_float4(0.f, 0.f, 0.f, 0.f);  // sum w*rstd*x
    float4 acc1p = make_float4(0.f, 0.f, 0.f, 0.f);
    float4 accMx = make_float4(-INFINITY, -INFINITY, -INFINITY, -INFINITY);
    float4 accMn = make_float4( INFINITY,  INFINITY,  INFINITY,  INFINITY);
    float m0 = -INFINITY, l0 = 0.f, K0 = 0.f;
    float m1 = -INFINITY, l1 = 0.f, K1 = 0.f;

    if (s0 < s1) {
        const float* xbase = tokens + (size_t)b * (SEQ + 1) * H + H;
        float4 xa[G];
#pragma unroll
        for (int g = 0; g < G; g++) {
            int s = min(s0 + g, s1 - 1);
            xa[g] = *(const float4*)&xbase[(size_t)s * H + h0];
        }

        int p = 0;
        for (int base = s0; base < s1; base += G, p ^= 1) {
            // ---- stage A: per-thread partials, packed v[4g+k] ----
            float v[32];
#pragma unroll
            for (int g = 0; g < G; g++) {
                float4 x = xa[g];
                v[4 * g + 0] = (x.x + x.y) + (x.z + x.w);
                v[4 * g + 1] = fmaf(x.x, x.x, fmaf(x.y, x.y, fmaf(x.z, x.z, x.w * x.w)));
                v[4 * g + 2] = fmaf(qg0.x, x.x, fmaf(qg0.y, x.y, fmaf(qg0.z, x.z, qg0.w * x.w)));
                v[4 * g + 3] = fmaf(qg1.x, x.x, fmaf(qg1.y, x.y, fmaf(qg1.z, x.z, qg1.w * x.w)));
            }
            // prefetch next group (overlaps reduction latency)
            float4 xb[G];
            const int nb = base + G;
            if (nb < s1) {
#pragma unroll
                for (int g = 0; g < G; g++) {
                    int s = min(nb + g, s1 - 1);
                    xb[g] = *(const float4*)&xbase[(size_t)s * H + h0];
                }
            } else {
#pragma unroll
                for (int g = 0; g < G; g++) xb[g] = make_float4(0.f, 0.f, 0.f, 0.f);
            }

            // ---- warp transpose reduce: lane L ends with warp-total of v[L] ----
#pragma unroll
            for (int off = 16, n = 32; off >= 1; off >>= 1, n >>= 1) {
                const bool hi = (lane & off) != 0;
#pragma unroll
                for (int i = 0; i < 32; i++) {
                    if (i < n / 2) {
                        float a = v[i], bvv = v[i + n / 2];
                        float send = hi ? a : bvv;
                        float keep = hi ? bvv : a;
                        v[i] = keep + __shfl_xor_sync(0xffffffffu, send, off);
                    }
                }
            }
            sredS[p][wid][lane] = v[0];
            __syncthreads();

            // ---- stage B: redundant per warp; token g8 = lane & 7 ----
            const int g8 = lane & 7;
            float4 vv = make_float4(0.f, 0.f, 0.f, 0.f);
#pragma unroll
            for (int w = 0; w < NW; w++) {
                float4 u = *(const float4*)&sredS[p][w][4 * g8];
                vv.x += u.x; vv.y += u.y; vv.z += u.z; vv.w += u.w;
            }
            const bool valid = (base + g8) < s1;
            float mu   = vv.x * (1.f / H);
            float var  = vv.y * (1.f / H) - mu * mu;
            float rstd = rsqrtf(var + 1e-5f);
            float z0 = valid ? (rstd * (vv.z - mu * S0) + C0) * SCALE : -INFINITY;
            float z1 = valid ? (rstd * (vv.w - mu * S1) + C1) * SCALE : -INFINITY;
            float gm0 = z0, gm1 = z1;
#pragma unroll
            for (int o = 4; o > 0; o >>= 1) {
                gm0 = fmaxf(gm0, __shfl_xor_sync(0xffffffffu, gm0, o, 8));
                gm1 = fmaxf(gm1, __shfl_xor_sync(0xffffffffu, gm1, o, 8));
            }
            float nm0 = fmaxf(m0, gm0), nm1 = fmaxf(m1, gm1);
            float f0 = __expf(m0 - nm0), f1 = __expf(m1 - nm1);
            float w0v = valid ? __expf(z0 - nm0) : 0.f;
            float w1v = valid ? __expf(z1 - nm1) : 0.f;
            float c0 = w0v * rstd, c1 = w1v * rstd;     // broadcast coefficients
            float k0p = c0 * mu, k1p = c1 * mu;
            float ws0 = w0v, ws1 = w1v, ks0 = k0p, ks1 = k1p;
#pragma unroll
            for (int o = 4; o > 0; o >>= 1) {
                ws0 += __shfl_xor_sync(0xffffffffu, ws0, o, 8);
                ws1 += __shfl_xor_sync(0xffffffffu, ws1, o, 8);
                ks0 += __shfl_xor_sync(0xffffffffu, ks0, o, 8);
                ks1 += __shfl_xor_sync(0xffffffffu, ks1, o, 8);
            }
            l0 = l0 * f0 + ws0; K0 = K0 * f0 + ks0; m0 = nm0;
            l1 = l1 * f1 + ws1; K1 = K1 * f1 + ks1; m1 = nm1;

            // ---- stage C: accumulate 8 tokens (linearized: 2 FMA/elem) ----
            acc0p.x *= f0; acc0p.y *= f0; acc0p.z *= f0; acc0p.w *= f0;
            acc1p.x *= f1; acc1p.y *= f1; acc1p.z *= f1; acc1p.w *= f1;
            const int gmax = min(G, s1 - base);
#pragma unroll
            for (int g = 0; g < G; g++) {
                float c0g = __shfl_sync(0xffffffffu, c0, g);
                float c1g = __shfl_sync(0xffffffffu, c1, g);
                if (g < gmax) {
                    float4 x = xa[g];
                    accS.x += x.x; accS.y += x.y; accS.z += x.z; accS.w += x.w;
                    accMx.x = fmaxf(accMx.x, x.x); accMx.y = fmaxf(accMx.y, x.y);
                    accMx.z = fmaxf(accMx.z, x.z); accMx.w = fmaxf(accMx.w, x.w);
                    accMn.x = fminf(accMn.x, x.x); accMn.y = fminf(accMn.y, x.y);
                    accMn.z = fminf(accMn.z, x.z); accMn.w = fminf(accMn.w, x.w);
                    acc0p.x = fmaf(c0g, x.x, acc0p.x); acc0p.y = fmaf(c0g, x.y, acc0p.y);
                    acc0p.z = fmaf(c0g, x.z, acc0p.z); acc0p.w = fmaf(c0g, x.w, acc0p.w);
                    acc1p.x = fmaf(c1g, x.x, acc1p.x); acc1p.y = fmaf(c1g, x.y, acc1p.y);
                    acc1p.z = fmaf(c1g, x.z, acc1p.z); acc1p.w = fmaf(c1g, x.w, acc1p.w);
                }
                xa[g] = xb[g];
            }
        }
    }

    // epilogue: reconstruct Σ w*xn = gv*(acc' - K) + lbv*l
    float4 stA0, stA1;
    stA0.x = fmaf(gv.x, acc0p.x - K0, lbv.x * l0);
    stA0.y = fmaf(gv.y, acc0p.y - K0, lbv.y * l0);
    stA0.z = fmaf(gv.z, acc0p.z - K0, lbv.z * l0);
    stA0.w = fmaf(gv.w, acc0p.w - K0, lbv.w * l0);
    stA1.x = fmaf(gv.x, acc1p.x - K1, lbv.x * l1);
    stA1.y = fmaf(gv.y, acc1p.y - K1, lbv.y * l1);
    stA1.z = fmaf(gv.z, acc1p.z - K1, lbv.z * l1);
    stA1.w = fmaf(gv.w, acc1p.w - K1, lbv.w * l1);

    *(float4*)&g_psum [b][c][h0] = accS;
    *(float4*)&g_pmax [b][c][h0] = accMx;
    *(float4*)&g_pmin [b][c][h0] = accMn;
    *(float4*)&g_pacc0[b][c][h0] = stA0;
    *(float4*)&g_pacc1[b][c][h0] = stA1;
    if (t == 0) {
        g_pm[b][c][0] = m0; g_pl[b][c][0] = l0;
        g_pm[b][c][1] = m1; g_pl[b][c][1] = l1;
    }
}

// ---------------- kernel 2: merge partials, build pooled vectors (float4) ------------
__global__ __launch_bounds__(192) void combine_pass(
    const float* __restrict__ tokens, const int* __restrict__ lengths)
{
    const int b = blockIdx.x, t = threadIdx.x;
    __shared__ float w0c[NCHUNK], w1c[NCHUNK];
    if (t < 32) {
        float mm0 = g_pm[b][t][0], ll0 = g_pl[b][t][0];
        float mm1 = g_pm[b][t][1], ll1 = g_pl[b][t][1];
        float M0 = mm0, M1 = mm1;
#pragma unroll
        for (int o = 16; o > 0; o >>= 1) {
            M0 = fmaxf(M0, __shfl_xor_sync(0xffffffffu, M0, o));
            M1 = fmaxf(M1, __shfl_xor_sync(0xffffffffu, M1, o));
        }
        float e0 = __expf(mm0 - M0), e1 = __expf(mm1 - M1);
        float L0 = e0 * ll0, L1 = e1 * ll1;
#pragma unroll
        for (int o = 16; o > 0; o >>= 1) {
            L0 += __shfl_xor_sync(0xffffffffu, L0, o);
            L1 += __shfl_xor_sync(0xffffffffu, L1, o);
        }
        w0c[t] = e0 / L0;
        w1c[t] = e1 / L1;
    }
    __syncthreads();
    const float inv_len = 1.f / (float)lengths[b];
    const int h0 = 4 * t;
    float4 sm = make_float4(0.f, 0.f, 0.f, 0.f);
    float4 a0 = sm, a1 = sm;
    float4 mx = make_float4(-INFINITY, -INFINITY, -INFINITY, -INFINITY);
    float4 mn = make_float4( INFINITY,  INFINITY,  INFINITY,  INFINITY);
#pragma unroll 4
    for (int c = 0; c < NCHUNK; c++) {
        float4 u = *(const float4*)&g_psum[b][c][h0];
        sm.x += u.x; sm.y += u.y; sm.z += u.z; sm.w += u.w;
        float4 vx = *(const float4*)&g_pmax[b][c][h0];
        mx.x = fmaxf(mx.x, vx.x); mx.y = fmaxf(mx.y, vx.y);
        mx.z = fmaxf(mx.z, vx.z); mx.w = fmaxf(mx.w, vx.w);
        float4 vn = *(const float4*)&g_pmin[b][c][h0];
        mn.x = fminf(mn.x, vn.x); mn.y = fminf(mn.y, vn.y);
        mn.z = fminf(mn.z, vn.z); mn.w = fminf(mn.w, vn.w);
        float w0 = w0c[c], w1 = w1c[c];
        float4 p0 = *(const float4*)&g_pacc0[b][c][h0];
        a0.x = fmaf(p0.x, w0, a0.x); a0.y = fmaf(p0.y, w0, a0.y);
        a0.z = fmaf(p0.z, w0, a0.z); a0.w = fmaf(p0.w, w0, a0.w);
        float4 p1 = *(const float4*)&g_pacc1[b][c][h0];
        a1.x = fmaf(p1.x, w1, a1.x); a1.y = fmaf(p1.y, w1, a1.y);
        a1.z = fmaf(p1.z, w1, a1.z); a1.w = fmaf(p1.w, w1, a1.w);
    }
    sm.x *= inv_len; sm.y *= inv_len; sm.z *= inv_len; sm.w *= inv_len;
    *(float4*)&g_pooled[0][b][h0]         = sm;
    *(float4*)&g_pooled[0][b][H + h0]     = mx;
    *(float4*)&g_pooled[0][b][2 * H + h0] = mn;
    *(float4*)&g_pooled[1][b][h0]         = a0;
    *(float4*)&g_pooled[1][b][H + h0]     = a1;
    *(float4*)&g_pooled[1][b][2 * H + h0] =
        *(const float4*)&tokens[(size_t)b * (SEQ + 1) * H + h0];  // clf
}

// ---------------- full-K GEMM with fused epilogue (bias + GELU or bias + store) ------
template <int K, bool FINAL>
__global__ __launch_bounds__(256) void gemm_fused(
    const float* __restrict__ W0, const float* __restrict__ W1,
    const float* __restrict__ bias0, const float* __restrict__ bias1,
    float* __restrict__ out)
{
    __shared__ float  sP[256][20];
    __shared__ float4 sAcc[8][BATCH][4];
    const int br = blockIdx.y;
    const int j0 = blockIdx.x * 16;
    const int t  = threadIdx.x;
    const int jq = t & 3, kg = t >> 2;   // 64 k-groups x 4 k each per tile
    const float* W    = br ? W1 : W0;
    const float* bias = br ? bias1 : bias0;
    const float* P    = FINAL ? &g_hid[br][0][0] : &g_pooled[br][0][0];

    float4 acc[BATCH];
#pragma unroll
    for (int m = 0; m < BATCH; m++) acc[m] = make_float4(0.f, 0.f, 0.f, 0.f);

    for (int k0 = 0; k0 < K; k0 += 256) {
#pragma unroll
        for (int r = 0; r < BATCH; r++) {
            int idx = t + r * 256;
            sP[idx & 255][idx >> 8] = P[(size_t)(idx >> 8) * K + k0 + (idx & 255)];
        }
        __syncthreads();
        const float* Wp = W + (size_t)(k0 + kg * 4) * H + j0 + jq * 4;
#pragma unroll
        for (int kk = 0; kk < 4; kk++) {
            float4 w = *(const float4*)(Wp + (size_t)kk * H);
            const float* prow = &sP[kg * 4 + kk][0];
#pragma unroll
            for (int m4 = 0; m4 < BATCH; m4 += 4) {
                float4 pv = *(const float4*)(prow + m4);
                float pm[4] = {pv.x, pv.y, pv.z, pv.w};
#pragma unroll
                for (int u = 0; u < 4; u++) {
                    acc[m4 + u].x = fmaf(pm[u], w.x, acc[m4 + u].x);
                    acc[m4 + u].y = fmaf(pm[u], w.y, acc[m4 + u].y);
                    acc[m4 + u].z = fmaf(pm[u], w.z, acc[m4 + u].z);
                    acc[m4 + u].w = fmaf(pm[u], w.w, acc[m4 + u].w);
                }
            }
        }
        __syncthreads();
    }

    // intra-warp reduce over the 8 kg values per warp (lanes share jq mod 4)
#pragma unroll
    for (int m = 0; m < BATCH; m++) {
#pragma unroll
        for (int off = 4; off <= 16; off <<= 1) {
            acc[m].x += __shfl_xor_sync(0xffffffffu, acc[m].x, off);
            acc[m].y += __shfl_xor_sync(0xffffffffu, acc[m].y, off);
            acc[m].z += __shfl_xor_sync(0xffffffffu, acc[m].z, off);
            acc[m].w += __shfl_xor_sync(0xffffffffu, acc[m].w, off);
        }
    }
    const int wrp = t >> 5, lane = t & 31;
    if (lane < 4) {
#pragma unroll
        for (int m = 0; m < BATCH; m++) sAcc[wrp][m][lane] = acc[m];
    }
    __syncthreads();

    if (t < 64) {
        const int m = t >> 2, jq2 = t & 3;
        float4 s = make_float4(0.f, 0.f, 0.f, 0.f);
#pragma unroll
        for (int w = 0; w < 8; w++) {
            float4 u = sAcc[w][m][jq2];
            s.x += u.x; s.y += u.y; s.z += u.z; s.w += u.w;
        }
        float4 bb = *(const float4*)&bias[j0 + jq2 * 4];
        s.x += bb.x; s.y += bb.y; s.z += bb.z; s.w += bb.w;
        if (FINAL) {
            *(float4*)&out[(size_t)m * (2 * H) + br * H + j0 + jq2 * 4] = s;
        } else {
            s.x = 0.5f * s.x * (1.f + erff(s.x * 0.7071067811865476f));
            s.y = 0.5f * s.y * (1.f + erff(s.y * 0.7071067811865476f));
            s.z = 0.5f * s.z * (1.f + erff(s.z * 0.7071067811865476f));
            s.w = 0.5f * s.w * (1.f + erff(s.w * 0.7071067811865476f));
            *(float4*)&g_hid[br][m][j0 + jq2 * 4] = s;
        }
    }
}

// ---------------- launch ----------------
extern "C" void kernel_launch(void* const* d_in, const int* in_sizes, int n_in,
                              void* d_out, int out_size)
{
    const float* tokens = (const float*)d_in[0];
    const int*   lengths= (const int*)  d_in[1];
    const float* q      = (const float*)d_in[2];
    const float* ln_g   = (const float*)d_in[3];
    const float* ln_b   = (const float*)d_in[4];
    const float* w1a    = (const float*)d_in[5];
    const float* b1a    = (const float*)d_in[6];
    const float* w1b    = (const float*)d_in[7];
    const float* b1b    = (const float*)d_in[8];
    const float* w2a    = (const float*)d_in[9];
    const float* b2a    = (const float*)d_in[10];
    const float* w2b    = (const float*)d_in[11];
    const float* b2b    = (const float*)d_in[12];
    float* out = (float*)d_out;

    main_pass<<<dim3(NCHUNK, BATCH), NT>>>(tokens, lengths, q, ln_g, ln_b);
    combine_pass<<<BATCH, 192>>>(tokens, lengths);
    gemm_fused<3 * H, false><<<dim3(H / 16, 2), 256>>>(w1a, w2a, b1a, b2a, nullptr);
    gemm_fused<H,     true ><<<dim3(H / 16, 2), 256>>>(w1b, w2b, b1b, b2b, out);
}

// round 7
// speedup vs baseline: 1.0657x; 1.0657x over previous
#include <cuda_runtime.h>
#include <math.h>

#define H      768
#define BATCH  16
#define SEQ    4096
#define NCHUNK 32
#define CHUNK  (SEQ / NCHUNK)      // 128
#define NT     192                 // main_pass threads (768/4)
#define NW     (NT / 32)           // 6 warps
#define G      8                   // tokens per group
#define SCALE  0.03608439182435161f  // 768^-0.5
#define KSPLA  12                  // layer-A k-split (KC=192)
#define KSPLB  6                   // layer-B k-split (KC=128)

// ---------------- scratch (static device arrays, allowed) ----------------
__device__ float g_psum [BATCH][NCHUNK][H];
__device__ float g_pmax [BATCH][NCHUNK][H];
__device__ float g_pmin [BATCH][NCHUNK][H];
__device__ float g_pacc0[BATCH][NCHUNK][H];
__device__ float g_pacc1[BATCH][NCHUNK][H];
__device__ float g_pm   [BATCH][NCHUNK][2];
__device__ float g_pl   [BATCH][NCHUNK][2];
__device__ float g_pooled[2][BATCH][3 * H];
__device__ float g_partA [2][KSPLA][BATCH][H];
__device__ float g_partB [2][KSPLB][BATCH][H];

// ---------------- kernel 1: fused LN + online-softmax-attn + pooling ----------------
__global__ __launch_bounds__(NT, 2) void main_pass(
    const float* __restrict__ tokens, const int* __restrict__ lengths,
    const float* __restrict__ q, const float* __restrict__ ln_g,
    const float* __restrict__ ln_b)
{
    const int b = blockIdx.y, c = blockIdx.x, t = threadIdx.x;
    const int wid = t >> 5, lane = t & 31;
    const int h0 = 4 * t;
    __shared__ float  sredS[2][NW][32];   // double-buffered: 1 barrier per group
    __shared__ float4 sred4[NW];

    const int len = lengths[b];
    const int s0  = c * CHUNK;
    const int s1  = min(s0 + CHUNK, len);

    const float4 gv  = *(const float4*)&ln_g[h0];
    const float4 lbv = *(const float4*)&ln_b[h0];
    const float4 q0v = *(const float4*)&q[h0];
    const float4 q1v = *(const float4*)&q[H + h0];
    const float4 qg0 = make_float4(q0v.x * gv.x, q0v.y * gv.y, q0v.z * gv.z, q0v.w * gv.w);
    const float4 qg1 = make_float4(q1v.x * gv.x, q1v.y * gv.y, q1v.z * gv.z, q1v.w * gv.w);

    float S0, S1, C0, C1;
    {
        float a = (qg0.x + qg0.y) + (qg0.z + qg0.w);
        float d = (qg1.x + qg1.y) + (qg1.z + qg1.w);
        float e = fmaf(q0v.x, lbv.x, fmaf(q0v.y, lbv.y, fmaf(q0v.z, lbv.z, q0v.w * lbv.w)));
        float f = fmaf(q1v.x, lbv.x, fmaf(q1v.y, lbv.y, fmaf(q1v.z, lbv.z, q1v.w * lbv.w)));
#pragma unroll
        for (int o = 16; o > 0; o >>= 1) {
            a += __shfl_xor_sync(0xffffffffu, a, o);
            d += __shfl_xor_sync(0xffffffffu, d, o);
            e += __shfl_xor_sync(0xffffffffu, e, o);
            f += __shfl_xor_sync(0xffffffffu, f, o);
        }
        if (lane == 0) sred4[wid] = make_float4(a, d, e, f);
        __syncthreads();
        float4 v = sred4[0];
#pragma unroll
        for (int w = 1; w < NW; w++) {
            float4 u = sred4[w]; v.x += u.x; v.y += u.y; v.z += u.z; v.w += u.w;
        }
        S0 = v.x; S1 = v.y; C0 = v.z; C1 = v.w;
        __syncthreads();
    }

    float4 accS  = make_float4(0.f, 0.f, 0.f, 0.f);
    float4 acc0p = make_float4(0.f, 0.f, 0.f, 0.f);  // sum w*rstd*x
    float4 acc1p = make_float4(0.f, 0.f, 0.f, 0.f);
    float4 accMx = make_float4(-INFINITY, -INFINITY, -INFINITY, -INFINITY);
    float4 accMn = make_float4( INFINITY,  INFINITY,  INFINITY,  INFINITY);
    float m0 = -INFINITY, l0 = 0.f, K0 = 0.f;
    float m1 = -INFINITY, l1 = 0.f, K1 = 0.f;

    if (s0 < s1) {
        const float* xbase = tokens + (size_t)b * (SEQ + 1) * H + H;
        float4 xa[G];
#pragma unroll
        for (int g = 0; g < G; g++) {
            int s = min(s0 + g, s1 - 1);
            xa[g] = *(const float4*)&xbase[(size_t)s * H + h0];
        }

        int p = 0;
        for (int base = s0; base < s1; base += G, p ^= 1) {
            float v[32];
#pragma unroll
            for (int g = 0; g < G; g++) {
                float4 x = xa[g];
                v[4 * g + 0] = (x.x + x.y) + (x.z + x.w);
                v[4 * g + 1] = fmaf(x.x, x.x, fmaf(x.y, x.y, fmaf(x.z, x.z, x.w * x.w)));
                v[4 * g + 2] = fmaf(qg0.x, x.x, fmaf(qg0.y, x.y, fmaf(qg0.z, x.z, qg0.w * x.w)));
                v[4 * g + 3] = fmaf(qg1.x, x.x, fmaf(qg1.y, x.y, fmaf(qg1.z, x.z, qg1.w * x.w)));
            }
            float4 xb[G];
            const int nb = base + G;
            if (nb < s1) {
#pragma unroll
                for (int g = 0; g < G; g++) {
                    int s = min(nb + g, s1 - 1);
                    xb[g] = *(const float4*)&xbase[(size_t)s * H + h0];
                }
            } else {
#pragma unroll
                for (int g = 0; g < G; g++) xb[g] = make_float4(0.f, 0.f, 0.f, 0.f);
            }

#pragma unroll
            for (int off = 16, n = 32; off >= 1; off >>= 1, n >>= 1) {
                const bool hi = (lane & off) != 0;
#pragma unroll
                for (int i = 0; i < 32; i++) {
                    if (i < n / 2) {
                        float a = v[i], bvv = v[i + n / 2];
                        float send = hi ? a : bvv;
                        float keep = hi ? bvv : a;
                        v[i] = keep + __shfl_xor_sync(0xffffffffu, send, off);
                    }
                }
            }
            sredS[p][wid][lane] = v[0];
            __syncthreads();

            const int g8 = lane & 7;
            float4 vv = make_float4(0.f, 0.f, 0.f, 0.f);
#pragma unroll
            for (int w = 0; w < NW; w++) {
                float4 u = *(const float4*)&sredS[p][w][4 * g8];
                vv.x += u.x; vv.y += u.y; vv.z += u.z; vv.w += u.w;
            }
            const bool valid = (base + g8) < s1;
            float mu   = vv.x * (1.f / H);
            float var  = vv.y * (1.f / H) - mu * mu;
            float rstd = rsqrtf(var + 1e-5f);
            float z0 = valid ? (rstd * (vv.z - mu * S0) + C0) * SCALE : -INFINITY;
            float z1 = valid ? (rstd * (vv.w - mu * S1) + C1) * SCALE : -INFINITY;
            float gm0 = z0, gm1 = z1;
#pragma unroll
            for (int o = 4; o > 0; o >>= 1) {
                gm0 = fmaxf(gm0, __shfl_xor_sync(0xffffffffu, gm0, o, 8));
                gm1 = fmaxf(gm1, __shfl_xor_sync(0xffffffffu, gm1, o, 8));
            }
            float nm0 = fmaxf(m0, gm0), nm1 = fmaxf(m1, gm1);
            float f0 = __expf(m0 - nm0), f1 = __expf(m1 - nm1);
            float w0v = valid ? __expf(z0 - nm0) : 0.f;
            float w1v = valid ? __expf(z1 - nm1) : 0.f;
            float c0 = w0v * rstd, c1 = w1v * rstd;
            float k0p = c0 * mu, k1p = c1 * mu;
            float ws0 = w0v, ws1 = w1v, ks0 = k0p, ks1 = k1p;
#pragma unroll
            for (int o = 4; o > 0; o >>= 1) {
                ws0 += __shfl_xor_sync(0xffffffffu, ws0, o, 8);
                ws1 += __shfl_xor_sync(0xffffffffu, ws1, o, 8);
                ks0 += __shfl_xor_sync(0xffffffffu, ks0, o, 8);
                ks1 += __shfl_xor_sync(0xffffffffu, ks1, o, 8);
            }
            l0 = l0 * f0 + ws0; K0 = K0 * f0 + ks0; m0 = nm0;
            l1 = l1 * f1 + ws1; K1 = K1 * f1 + ks1; m1 = nm1;

            acc0p.x *= f0; acc0p.y *= f0; acc0p.z *= f0; acc0p.w *= f0;
            acc1p.x *= f1; acc1p.y *= f1; acc1p.z *= f1; acc1p.w *= f1;
            const int gmax = min(G, s1 - base);
#pragma unroll
            for (int g = 0; g < G; g++) {
                float c0g = __shfl_sync(0xffffffffu, c0, g);
                float c1g = __shfl_sync(0xffffffffu, c1, g);
                if (g < gmax) {
                    float4 x = xa[g];
                    accS.x += x.x; accS.y += x.y; accS.z += x.z; accS.w += x.w;
                    accMx.x = fmaxf(accMx.x, x.x); accMx.y = fmaxf(accMx.y, x.y);
                    accMx.z = fmaxf(accMx.z, x.z); accMx.w = fmaxf(accMx.w, x.w);
                    accMn.x = fminf(accMn.x, x.x); accMn.y = fminf(accMn.y, x.y);
                    accMn.z = fminf(accMn.z, x.z); accMn.w = fminf(accMn.w, x.w);
                    acc0p.x = fmaf(c0g, x.x, acc0p.x); acc0p.y = fmaf(c0g, x.y, acc0p.y);
                    acc0p.z = fmaf(c0g, x.z, acc0p.z); acc0p.w = fmaf(c0g, x.w, acc0p.w);
                    acc1p.x = fmaf(c1g, x.x, acc1p.x); acc1p.y = fmaf(c1g, x.y, acc1p.y);
                    acc1p.z = fmaf(c1g, x.z, acc1p.z); acc1p.w = fmaf(c1g, x.w, acc1p.w);
                }
                xa[g] = xb[g];
            }
        }
    }

    float4 stA0, stA1;
    stA0.x = fmaf(gv.x, acc0p.x - K0, lbv.x * l0);
    stA0.y = fmaf(gv.y, acc0p.y - K0, lbv.y * l0);
    stA0.z = fmaf(gv.z, acc0p.z - K0, lbv.z * l0);
    stA0.w = fmaf(gv.w, acc0p.w - K0, lbv.w * l0);
    stA1.x = fmaf(gv.x, acc1p.x - K1, lbv.x * l1);
    stA1.y = fmaf(gv.y, acc1p.y - K1, lbv.y * l1);
    stA1.z = fmaf(gv.z, acc1p.z - K1, lbv.z * l1);
    stA1.w = fmaf(gv.w, acc1p.w - K1, lbv.w * l1);

    *(float4*)&g_psum [b][c][h0] = accS;
    *(float4*)&g_pmax [b][c][h0] = accMx;
    *(float4*)&g_pmin [b][c][h0] = accMn;
    *(float4*)&g_pacc0[b][c][h0] = stA0;
    *(float4*)&g_pacc1[b][c][h0] = stA1;
    if (t == 0) {
        g_pm[b][c][0] = m0; g_pl[b][c][0] = l0;
        g_pm[b][c][1] = m1; g_pl[b][c][1] = l1;
    }
}

// ---------------- kernel 2: merge partials, build pooled vectors (float4) ------------
__global__ __launch_bounds__(192) void combine_pass(
    const float* __restrict__ tokens, const int* __restrict__ lengths)
{
    const int b = blockIdx.x, t = threadIdx.x;
    __shared__ float w0c[NCHUNK], w1c[NCHUNK];
    if (t < 32) {
        float mm0 = g_pm[b][t][0], ll0 = g_pl[b][t][0];
        float mm1 = g_pm[b][t][1], ll1 = g_pl[b][t][1];
        float M0 = mm0, M1 = mm1;
#pragma unroll
        for (int o = 16; o > 0; o >>= 1) {
            M0 = fmaxf(M0, __shfl_xor_sync(0xffffffffu, M0, o));
            M1 = fmaxf(M1, __shfl_xor_sync(0xffffffffu, M1, o));
        }
        float e0 = __expf(mm0 - M0), e1 = __expf(mm1 - M1);
        float L0 = e0 * ll0, L1 = e1 * ll1;
#pragma unroll
        for (int o = 16; o > 0; o >>= 1) {
            L0 += __shfl_xor_sync(0xffffffffu, L0, o);
            L1 += __shfl_xor_sync(0xffffffffu, L1, o);
        }
        w0c[t] = e0 / L0;
        w1c[t] = e1 / L1;
    }
    __syncthreads();
    const float inv_len = 1.f / (float)lengths[b];
    const int h0 = 4 * t;
    float4 sm = make_float4(0.f, 0.f, 0.f, 0.f);
    float4 a0 = sm, a1 = sm;
    float4 mx = make_float4(-INFINITY, -INFINITY, -INFINITY, -INFINITY);
    float4 mn = make_float4( INFINITY,  INFINITY,  INFINITY,  INFINITY);
#pragma unroll 4
    for (int c = 0; c < NCHUNK; c++) {
        float4 u = *(const float4*)&g_psum[b][c][h0];
        sm.x += u.x; sm.y += u.y; sm.z += u.z; sm.w += u.w;
        float4 vx = *(const float4*)&g_pmax[b][c][h0];
        mx.x = fmaxf(mx.x, vx.x); mx.y = fmaxf(mx.y, vx.y);
        mx.z = fmaxf(mx.z, vx.z); mx.w = fmaxf(mx.w, vx.w);
        float4 vn = *(const float4*)&g_pmin[b][c][h0];
        mn.x = fminf(mn.x, vn.x); mn.y = fminf(mn.y, vn.y);
        mn.z = fminf(mn.z, vn.z); mn.w = fminf(mn.w, vn.w);
        float w0 = w0c[c], w1 = w1c[c];
        float4 p0 = *(const float4*)&g_pacc0[b][c][h0];
        a0.x = fmaf(p0.x, w0, a0.x); a0.y = fmaf(p0.y, w0, a0.y);
        a0.z = fmaf(p0.z, w0, a0.z); a0.w = fmaf(p0.w, w0, a0.w);
        float4 p1 = *(const float4*)&g_pacc1[b][c][h0];
        a1.x = fmaf(p1.x, w1, a1.x); a1.y = fmaf(p1.y, w1, a1.y);
        a1.z = fmaf(p1.z, w1, a1.z); a1.w = fmaf(p1.w, w1, a1.w);
    }
    sm.x *= inv_len; sm.y *= inv_len; sm.z *= inv_len; sm.w *= inv_len;
    *(float4*)&g_pooled[0][b][h0]         = sm;
    *(float4*)&g_pooled[0][b][H + h0]     = mx;
    *(float4*)&g_pooled[0][b][2 * H + h0] = mn;
    *(float4*)&g_pooled[1][b][h0]         = a0;
    *(float4*)&g_pooled[1][b][H + h0]     = a1;
    *(float4*)&g_pooled[1][b][2 * H + h0] =
        *(const float4*)&tokens[(size_t)b * (SEQ + 1) * H + h0];  // clf
}

// ---------------- layer A: split-K partial GEMM (12 deterministic slots) -------------
template <int K, int KC>
__global__ __launch_bounds__(256) void gemm_partA(
    const float* __restrict__ W0, const float* __restrict__ W1)
{
    __shared__ __align__(16) char smemBuf[32768];
    float (*sP)[20] = (float (*)[20])smemBuf;
    float4 (*sAcc)[16][16] = (float4 (*)[16][16])smemBuf;

    const int br = blockIdx.z;
    const int j0 = blockIdx.x * 64;
    const int k0 = blockIdx.y * KC;
    const int t  = threadIdx.x;
    const float* W = br ? W1 : W0;
    const float* P = &g_pooled[br][0][0];

    for (int idx = t; idx < BATCH * KC; idx += 256) {
        int m = idx / KC, k = idx % KC;
        sP[k][m] = P[(size_t)m * K + k0 + k];
    }
    __syncthreads();

    const int jq = t & 15, jj = jq * 4;
    const int kg = t >> 4;
    const int kb = kg * (KC / 16);
    float4 acc[BATCH];
#pragma unroll
    for (int m = 0; m < BATCH; m++) acc[m] = make_float4(0.f, 0.f, 0.f, 0.f);

    const float* Wp = W + (size_t)(k0 + kb) * H + j0 + jj;
#pragma unroll 4
    for (int k = 0; k < KC / 16; k++) {
        const float4 w = *(const float4*)(Wp + (size_t)k * H);
        const float* prow = &sP[kb + k][0];
#pragma unroll
        for (int m4 = 0; m4 < BATCH; m4 += 4) {
            const float4 pv = *(const float4*)(prow + m4);
            float pm[4] = {pv.x, pv.y, pv.z, pv.w};
#pragma unroll
            for (int u = 0; u < 4; u++) {
                acc[m4 + u].x = fmaf(pm[u], w.x, acc[m4 + u].x);
                acc[m4 + u].y = fmaf(pm[u], w.y, acc[m4 + u].y);
                acc[m4 + u].z = fmaf(pm[u], w.z, acc[m4 + u].z);
                acc[m4 + u].w = fmaf(pm[u], w.w, acc[m4 + u].w);
            }
        }
    }
#pragma unroll
    for (int m = 0; m < BATCH; m++) {
        acc[m].x += __shfl_xor_sync(0xffffffffu, acc[m].x, 16);
        acc[m].y += __shfl_xor_sync(0xffffffffu, acc[m].y, 16);
        acc[m].z += __shfl_xor_sync(0xffffffffu, acc[m].z, 16);
        acc[m].w += __shfl_xor_sync(0xffffffffu, acc[m].w, 16);
    }
    __syncthreads();
    const int wrp = t >> 5, lane = t & 31;
    if (lane < 16) {
#pragma unroll
        for (int m = 0; m < BATCH; m++) sAcc[wrp][m][lane] = acc[m];
    }
    __syncthreads();
    const int m = t >> 4, jq2 = t & 15;
    float4 s = make_float4(0.f, 0.f, 0.f, 0.f);
#pragma unroll
    for (int w = 0; w < 8; w++) {
        float4 u = sAcc[w][m][jq2];
        s.x += u.x; s.y += u.y; s.z += u.z; s.w += u.w;
    }
    *(float4*)&g_partA[br][blockIdx.y][(size_t)m][j0 + jq2 * 4] = s;
}

// ---------------- layer B: fused (reduce A slots + bias + GELU) prologue, split-K ----
template <int K, int KC>
__global__ __launch_bounds__(256) void gemm_partB(
    const float* __restrict__ W0, const float* __restrict__ W1,
    const float* __restrict__ b1a, const float* __restrict__ b2a)
{
    __shared__ __align__(16) char smemBuf[32768];
    float (*sP)[20] = (float (*)[20])smemBuf;
    float4 (*sAcc)[16][16] = (float4 (*)[16][16])smemBuf;

    const int br = blockIdx.z;
    const int j0 = blockIdx.x * 64;
    const int k0 = blockIdx.y * KC;
    const int t  = threadIdx.x;
    const float* W    = br ? W1 : W0;
    const float* biasA = br ? b2a : b1a;

    // fused act: hid[m][k] = gelu(biasA[k] + sum_sl partA[br][sl][m][k])
    for (int idx = t; idx < BATCH * KC; idx += 256) {
        int m = idx / KC, k = idx % KC;
        float s = biasA[k0 + k];
#pragma unroll
        for (int sl = 0; sl < KSPLA; sl++) s += g_partA[br][sl][m][k0 + k];
        sP[k][m] = 0.5f * s * (1.f + erff(s * 0.7071067811865476f));
    }
    __syncthreads();

    const int jq = t & 15, jj = jq * 4;
    const int kg = t >> 4;
    const int kb = kg * (KC / 16);
    float4 acc[BATCH];
#pragma unroll
    for (int m = 0; m < BATCH; m++) acc[m] = make_float4(0.f, 0.f, 0.f, 0.f);

    const float* Wp = W + (size_t)(k0 + kb) * H + j0 + jj;
#pragma unroll 4
    for (int k = 0; k < KC / 16; k++) {
        const float4 w = *(const float4*)(Wp + (size_t)k * H);
        const float* prow = &sP[kb + k][0];
#pragma unroll
        for (int m4 = 0; m4 < BATCH; m4 += 4) {
            const float4 pv = *(const float4*)(prow + m4);
            float pm[4] = {pv.x, pv.y, pv.z, pv.w};
#pragma unroll
            for (int u = 0; u < 4; u++) {
                acc[m4 + u].x = fmaf(pm[u], w.x, acc[m4 + u].x);
                acc[m4 + u].y = fmaf(pm[u], w.y, acc[m4 + u].y);
                acc[m4 + u].z = fmaf(pm[u], w.z, acc[m4 + u].z);
                acc[m4 + u].w = fmaf(pm[u], w.w, acc[m4 + u].w);
            }
        }
    }
#pragma unroll
    for (int m = 0; m < BATCH; m++) {
        acc[m].x += __shfl_xor_sync(0xffffffffu, acc[m].x, 16);
        acc[m].y += __shfl_xor_sync(0xffffffffu, acc[m].y, 16);
        acc[m].z += __shfl_xor_sync(0xffffffffu, acc[m].z, 16);
        acc[m].w += __shfl_xor_sync(0xffffffffu, acc[m].w, 16);
    }
    __syncthreads();
    const int wrp = t >> 5, lane = t & 31;
    if (lane < 16) {
#pragma unroll
        for (int m = 0; m < BATCH; m++) sAcc[wrp][m][lane] = acc[m];
    }
    __syncthreads();
    const int m = t >> 4, jq2 = t & 15;
    float4 s = make_float4(0.f, 0.f, 0.f, 0.f);
#pragma unroll
    for (int w = 0; w < 8; w++) {
        float4 u = sAcc[w][m][jq2];
        s.x += u.x; s.y += u.y; s.z += u.z; s.w += u.w;
    }
    *(float4*)&g_partB[br][blockIdx.y][(size_t)m][j0 + jq2 * 4] = s;
}

// ---------------- final: reduce B slots + bias -> output ----------------
__global__ __launch_bounds__(256) void final_pass(
    const float* __restrict__ b1b, const float* __restrict__ b2b,
    float* __restrict__ out)
{
    const int id = blockIdx.x * 256 + threadIdx.x;
    const int j  = id % H;
    const int m  = (id / H) & (BATCH - 1);
    const int br = id / (H * BATCH);
    float s = (br ? b2b : b1b)[j];
#pragma unroll
    for (int sl = 0; sl < KSPLB; sl++) s += g_partB[br][sl][m][j];
    out[(size_t)m * (2 * H) + br * H + j] = s;
}

// ---------------- launch ----------------
extern "C" void kernel_launch(void* const* d_in, const int* in_sizes, int n_in,
                              void* d_out, int out_size)
{
    const float* tokens = (const float*)d_in[0];
    const int*   lengths= (const int*)  d_in[1];
    const float* q      = (const float*)d_in[2];
    const float* ln_g   = (const float*)d_in[3];
    const float* ln_b   = (const float*)d_in[4];
    const float* w1a    = (const float*)d_in[5];
    const float* b1a    = (const float*)d_in[6];
    const float* w1b    = (const float*)d_in[7];
    const float* b1b    = (const float*)d_in[8];
    const float* w2a    = (const float*)d_in[9];
    const float* b2a    = (const float*)d_in[10];
    const float* w2b    = (const float*)d_in[11];
    const float* b2b    = (const float*)d_in[12];
    float* out = (float*)d_out;

    main_pass<<<dim3(NCHUNK, BATCH), NT>>>(tokens, lengths, q, ln_g, ln_b);
    combine_pass<<<BATCH, 192>>>(tokens, lengths);
    gemm_partA<3 * H, 3 * H / KSPLA><<<dim3(H / 64, KSPLA, 2), 256>>>(w1a, w2a);
    gemm_partB<H, H / KSPLB><<<dim3(H / 64, KSPLB, 2), 256>>>(w1b, w2b, b1a, b2a);
    final_pass<<<(2 * BATCH * H) / 256, 256>>>(b1b, b2b, out);
}